// round 13
// baseline (speedup 1.0000x reference)
#include <cuda_runtime.h>
#include <cuda_fp16.h>
#include <cstdint>

// CARAFE: B=8, C=256, H=W=64, K=5, UP=2.
// out[b,c,2h+i,2w+j] = sum_{ki,kj} km[b,(i*2+j)*25+ki*5+kj,h,w] * x[b,c,h+ki-2,w+kj-2]
//
// R12 vs R11 (55.8us): HFMA2 channel-pairing. Channels share the per-pixel
// weights, so pack (c0,c1) in the halves of a half2 and use
//   acc += (w,w) * (x_c0, x_c1)        [fma.rn.f16x2, rt_SMSP=2, 2 MACs/instr]
// -> 200 HFMA2 per 4 channels instead of 400 FFMA: fma floor 48.4 -> ~25us.
// Precision: 3 accumulation chains (taps 0-8 / 9-16 / 17-24) + 1 HADD2 +
// fp32 cross-chain combine; expected norm rel_err ~7.5e-4 < 1e-3.
// Staging / schedule / barriers IDENTICAL to R11 (592 CTAs single wave,
// 28/27 static split, <=2 constant-bh segments, 2x64-thread independent
// groups with named barriers, NBUF=3 cp.async fp32 pipeline).

namespace {
constexpr int Hc = 64, Wc = 64;
constexpr int Kk = 5, QQ = 100;
constexpr int THREADS = 128;
constexpr int SROW = 72;                  // 4 halo + 64 + 4 halo
constexpr int GCH = 4;                    // channels per group per unit
constexpr int NBUF = 3;
constexpr int GBUF  = Kk * GCH * SROW;    // 1440 floats per group-buffer
constexpr int GBUFB = GBUF * 4;           // 5760 B
constexpr int GROWB = GCH * SROW * 4;     // smem bytes between kernel rows
constexpr int CH4 = Hc * Wc / 4;          // 1024 float4 per channel image
constexpr int NUNITS = 512 * 32;          // 16384
constexpr int NCTA = 592;                 // single wave on 148-152 SMs x 4 CTA
constexpr int NBIG = NUNITS - NCTA * 27;  // 400 CTAs take 28 units
constexpr int U4 = 8 * CH4;               // float4 stride of one unit (8 ch)
}

__device__ __forceinline__ void cp_async16(uint32_t dst, const float4* src, bool valid) {
    int sz = valid ? 16 : 0;
    asm volatile("cp.async.cg.shared.global [%0], [%1], 16, %2;"
                 :: "r"(dst), "l"(src), "r"(sz) : "memory");
}
__device__ __forceinline__ void cp_commit() {
    asm volatile("cp.async.commit_group;" ::: "memory");
}
template <int N>
__device__ __forceinline__ void cp_wait() {
    asm volatile("cp.async.wait_group %0;" :: "n"(N) : "memory");
}
__device__ __forceinline__ void group_bar(int id) {
    asm volatile("bar.sync %0, 64;" :: "r"(id) : "memory");
}

__global__ __launch_bounds__(THREADS, 4)
void carafe_kernel(const float* __restrict__ x,
                   const float* __restrict__ km,
                   float* __restrict__ out)
{
    const int tid = threadIdx.x;
    const int g   = tid >> 6;            // independent 64-thread group 0/1
    const int w   = tid & 63;            // pixel column (compute role)
    const int f   = tid & 15;            // staged float4 column (staging role)
    const int cig = (tid >> 4) & 3;      // staged channel within group

    __shared__ __align__(16) float sbuf[2 * NBUF * GBUF];

    float* sgrp = sbuf + g * (NBUF * GBUF);

    // ---- static work range ----
    const int cta   = blockIdx.x;
    const int n     = (cta < NBIG) ? 28 : 27;
    const int start = (cta < NBIG) ? cta * 28 : 27 * cta + NBIG;

    // ---- zero halo/pad columns of THIS group's buffers (group-local, once) ----
    for (int e = (tid & 63); e < NBUF * Kk * GCH * 8; e += 64) {
        int rc = e >> 3, cs = e & 7;
        int col = (cs < 4) ? cs : (64 + cs);
        sgrp[rc * SROW + col] = 0.f;
    }

    const float4* x4 = (const float4*)x;
    const uint32_t sg_u32 = (uint32_t)__cvta_generic_to_shared(sgrp);
    const uint32_t soff0  = (uint32_t)((cig * SROW + 4 * f + 4) * 4);

    int u = start, rem = n;
    bool first = true;

    #pragma unroll 1
    while (rem > 0) {
        const int bh = u >> 5;
        const int g0 = u & 31;
        const int b  = bh >> 6;
        const int h  = bh & 63;
        int cnt = 32 - g0; if (cnt > rem) cnt = rem;

        if (!first) group_bar(g + 1);
        first = false;

        // ---- hoisted per-segment staging constants (h fixed) ----
        bool rv[Kk]; int rb[Kk];
        #pragma unroll
        for (int k = 0; k < Kk; k++) {
            int gr = h - 2 + k;
            rv[k] = (unsigned)gr < (unsigned)Hc;
            rb[k] = (rv[k] ? gr : 0) * (Wc / 4) + f;
        }
        int cb4 = ((b << 8) + (g0 << 3) + (g << 2) + cig) * CH4;   // += U4 per unit

        // ---- prologue: issue units 0 (+1) ----
        #pragma unroll
        for (int k = 0; k < Kk; k++)
            cp_async16(sg_u32 + soff0 + k * GROWB, x4 + cb4 + rb[k], rv[k]);
        cp_commit();
        if (cnt > 1) {
            #pragma unroll
            for (int k = 0; k < Kk; k++)
                cp_async16(sg_u32 + GBUFB + soff0 + k * GROWB,
                           x4 + (cb4 + U4) + rb[k], rv[k]);
            cp_commit();
        }

        // ---- weights for this bh: fp32 -> duplicated half2 (100 regs) ----
        __half2 wh2[QQ];
        const float* kmp = km + ((size_t)b * QQ * Hc + h) * Wc + w;
        #pragma unroll
        for (int q = 0; q < QQ; q++)
            wh2[q] = __float2half2_rn(__ldg(kmp + (size_t)q * (Hc * Wc)));

        float* optr = out + ((size_t)((b << 8) + (g0 << 3) + (g << 2)) * 128
                             + 2 * h) * 128 + 2 * w;
        int cb4i = cb4 + 2 * U4;   // unit j+2 base
        int rdBuf = 0;

        #pragma unroll 1
        for (int j = 0; j < cnt; j++) {
            if (j + 1 < cnt) cp_wait<1>(); else cp_wait<0>();
            group_bar(g + 1);

            if (j + 2 < cnt) {
                int wr = rdBuf + 2; if (wr >= NBUF) wr -= NBUF;
                uint32_t d = sg_u32 + (uint32_t)wr * GBUFB + soff0;
                #pragma unroll
                for (int k = 0; k < Kk; k++)
                    cp_async16(d + k * GROWB, x4 + cb4i + rb[k], rv[k]);
                cp_commit();
                cb4i += U4;
            }

            // ---- compute 4 channels as 2 half2 channel-pairs ----
            const float* base = sgrp + rdBuf * GBUF + (w + 2);
            #pragma unroll
            for (int pr = 0; pr < 2; pr++) {
                const float* sp0 = base + (2 * pr) * SROW;     // channel c0
                const float* sp1 = sp0 + SROW;                 // channel c0+1

                const __half2 z = __float2half2_rn(0.f);
                __half2 A0=z,A1=z,A2=z,A3=z;   // taps 0..8
                __half2 B0=z,B1=z,B2=z,B3=z;   // taps 9..16
                __half2 C0=z,C1=z,C2=z,C3=z;   // taps 17..24

                #pragma unroll
                for (int k = 0; k < 25; k++) {
                    const int r = k / 5, jj = k % 5;
                    const int off = r * (GCH * SROW) + jj;
                    __half2 xp = __floats2half2_rn(sp0[off], sp1[off]);
                    if (k < 9) {
                        A0 = __hfma2(wh2[k],      xp, A0);
                        A1 = __hfma2(wh2[25 + k], xp, A1);
                        A2 = __hfma2(wh2[50 + k], xp, A2);
                        A3 = __hfma2(wh2[75 + k], xp, A3);
                    } else if (k < 17) {
                        B0 = __hfma2(wh2[k],      xp, B0);
                        B1 = __hfma2(wh2[25 + k], xp, B1);
                        B2 = __hfma2(wh2[50 + k], xp, B2);
                        B3 = __hfma2(wh2[75 + k], xp, B3);
                    } else {
                        C0 = __hfma2(wh2[k],      xp, C0);
                        C1 = __hfma2(wh2[25 + k], xp, C1);
                        C2 = __hfma2(wh2[50 + k], xp, C2);
                        C3 = __hfma2(wh2[75 + k], xp, C3);
                    }
                }

                // epilogue: (A+B) in fp16, cross-chain combine in fp32
                __half2 ab0 = __hadd2(A0, B0), ab1 = __hadd2(A1, B1);
                __half2 ab2 = __hadd2(A2, B2), ab3 = __hadd2(A3, B3);
                float v00 = __low2float(ab0)  + __low2float(C0);
                float v01 = __low2float(ab1)  + __low2float(C1);
                float v02 = __low2float(ab2)  + __low2float(C2);
                float v03 = __low2float(ab3)  + __low2float(C3);
                float v10 = __high2float(ab0) + __high2float(C0);
                float v11 = __high2float(ab1) + __high2float(C1);
                float v12 = __high2float(ab2) + __high2float(C2);
                float v13 = __high2float(ab3) + __high2float(C3);

                // subpixel u = i*2+j -> (2h+i, 2w+j); channels c0, c0+1
                float* o0 = optr + (size_t)(2 * pr) * (128 * 128);
                float* o1 = o0 + (128 * 128);
                *reinterpret_cast<float2*>(o0)       = make_float2(v00, v01);
                *reinterpret_cast<float2*>(o0 + 128) = make_float2(v02, v03);
                *reinterpret_cast<float2*>(o1)       = make_float2(v10, v11);
                *reinterpret_cast<float2*>(o1 + 128) = make_float2(v12, v13);
            }
            optr += (size_t)8 * (128 * 128);

            rdBuf++; if (rdBuf == NBUF) rdBuf = 0;
        }

        u += cnt; rem -= cnt;
    }
}

extern "C" void kernel_launch(void* const* d_in, const int* in_sizes, int n_in,
                              void* d_out, int out_size)
{
    const float* x  = (const float*)d_in[0];   // [8,256,64,64]
    const float* km = (const float*)d_in[1];   // [8,100,64,64]
    float* out = (float*)d_out;                // [8,256,128,128]

    carafe_kernel<<<NCTA, THREADS>>>(x, km, out);
}

// round 14
// speedup vs baseline: 1.3078x; 1.3078x over previous
#include <cuda_runtime.h>
#include <cuda_fp16.h>
#include <cstdint>

// CARAFE: B=8, C=256, H=W=64, K=5, UP=2.
// out[b,c,2h+i,2w+j] = sum_{ki,kj} km[b,(i*2+j)*25+ki*5+kj,h,w] * x[b,c,h+ki-2,w+kj-2]
//
// R13 vs R12 (65.7us, rel_err 5.6e-4 OK) / R11 (55.8us best):
// Binder is ISSUE bandwidth (R11: 560 instr/unit-thread @63% issue). Minimize
// instructions: stage fp16 CHANNEL-PAIRS in smem (convert once at staging:
// LDG.128 fp32 -> cvt.rn.f16x2.f32 -> STS.128), so the inner loop is pure
// 25 LDS.32(half2) + 100 HFMA2 per pair — no conversions, LDS count halved.
// Weights packed 2-taps-per-half2 (50 regs) and broadcast via half-lane
// selectors (.H0_H0/.H1_H1 fold). ~350 instr/unit-thread vs 560.
// Precision identical to R12: 3 fp16 chains (taps 0-8/9-16/17-24) + fp32
// cross-chain combine.
// Schedule as R11: 592 CTAs single wave, 28/27 split, <=2 constant-bh
// segments, 2x64-thread independent groups, named barriers, NBUF=3.

namespace {
constexpr int Hc = 64, Wc = 64;
constexpr int QQ = 100;
constexpr int THREADS = 128;
constexpr int CH4 = Hc * Wc / 4;          // 1024 float4 per channel image
constexpr int SROWH = 72;                 // half2 per staged row (4+64+4)
constexpr int PAIRH = 5 * SROWH;          // 360 half2 per pair-plane
constexpr int GBUFH = 2 * PAIRH;          // 720 half2 per buffer (2 pairs)
constexpr int NBUF  = 3;
constexpr int NUNITS = 512 * 32;          // 16384
constexpr int NCTA = 592;                 // single wave
constexpr int NBIG = NUNITS - NCTA * 27;  // 400 CTAs take 28 units
constexpr int U4 = 8 * CH4;               // float4 stride of one unit (8 ch)
}

__device__ __forceinline__ uint32_t pack_h2(float lo, float hi) {
    uint32_t r;   // cvt.rn.f16x2.f32 d, a, b : high<-a, low<-b
    asm("cvt.rn.f16x2.f32 %0, %1, %2;" : "=r"(r) : "f"(hi), "f"(lo));
    return r;
}
__device__ __forceinline__ __half2 u2h(uint32_t u) {
    return *reinterpret_cast<__half2*>(&u);
}
__device__ __forceinline__ __half2 blo(__half2 v) { return __half2half2(__low2half(v)); }
__device__ __forceinline__ __half2 bhi(__half2 v) { return __half2half2(__high2half(v)); }
__device__ __forceinline__ void group_bar(int id) {
    asm volatile("bar.sync %0, 64;" :: "r"(id) : "memory");
}

__global__ __launch_bounds__(THREADS, 4)
void carafe_kernel(const float* __restrict__ x,
                   const float* __restrict__ km,
                   float* __restrict__ out)
{
    const int tid = threadIdx.x;
    const int g   = tid >> 6;            // independent 64-thread group 0/1
    const int w   = tid & 63;            // pixel column / lane within group

    // 2 groups x NBUF buffers x [pair 2][row 5][72] half2
    __shared__ __align__(16) __half2 sbuf[2 * NBUF * GBUFH];
    __half2* sgrp = sbuf + g * (NBUF * GBUFH);

    // ---- static work range ----
    const int cta   = blockIdx.x;
    const int n     = (cta < NBIG) ? 28 : 27;
    const int start = (cta < NBIG) ? cta * 28 : 27 * cta + NBIG;

    // ---- zero halo cols (0..3, 68..71) of all buffers/pairs/rows, once ----
    for (int e = w; e < NBUF * 2 * 5 * 8; e += 64) {
        int rc = e >> 3, cs = e & 7;
        int col = (cs < 4) ? cs : (64 + cs);
        sgrp[rc * SROWH + col] = __half2half2(__float2half(0.f));
    }

    const float4* x4 = (const float4*)x;
    const float4 zf4 = make_float4(0.f, 0.f, 0.f, 0.f);

    // ---- per-lane staging tasks (constant shapes; offsets fixed per segment) ----
    // task A (all lanes): r = w>>4, col4 = w&15.  task B (lanes<16): r = 4, col4 = w.
    const int  rA   = w >> 4, cA4 = w & 15;
    const bool hasB = (w < 16);
    const int  dA01 = rA * SROWH + 4 + 4 * cA4;        // half2 index in buffer
    const int  dB01 = 4 * SROWH + 4 + 4 * w;           // (only lanes<16)

    int u = start, rem = n;
    bool first = true;

    #pragma unroll 1
    while (rem > 0) {
        const int bh = u >> 5;
        const int g0 = u & 31;
        const int b  = bh >> 6;
        const int h  = bh & 63;
        int cnt = 32 - g0; if (cnt > rem) cnt = rem;

        if (!first) group_bar(g + 1);   // prev segment's readers done
        first = false;

        // ---- hoisted per-segment staging addressing ----
        const int  grA = h - 2 + rA;
        const bool vA  = (unsigned)grA < (unsigned)Hc;
        const int  offA = (vA ? grA : 0) * 16 + cA4;
        const bool vB  = (h + 2) < Hc;
        const int  offB = (vB ? (h + 2) : 0) * 16 + (w & 15);

        int base4 = ((b << 8) + (g0 << 3) + (g << 2)) * CH4;   // += U4 per unit

        // ---- prologue: prefetch unit 0 into registers ----
        float4 pA[4], pB[4];
        #pragma unroll
        for (int c = 0; c < 4; c++)
            pA[c] = vA ? __ldg(x4 + base4 + c * CH4 + offA) : zf4;
        if (hasB) {
            #pragma unroll
            for (int c = 0; c < 4; c++)
                pB[c] = vB ? __ldg(x4 + base4 + c * CH4 + offB) : zf4;
        }

        // ---- weights for this bh: pack 2 taps per half2 (50 regs) ----
        const float* kmp = km + ((size_t)b * QQ * Hc + h) * Wc + w;
        __half2 wpk[48];
        #pragma unroll
        for (int uu = 0; uu < 4; uu++)
            #pragma unroll
            for (int p = 0; p < 12; p++)
                wpk[uu * 12 + p] = u2h(pack_h2(
                    __ldg(kmp + (size_t)(uu * 25 + 2 * p)     * (Hc * Wc)),
                    __ldg(kmp + (size_t)(uu * 25 + 2 * p + 1) * (Hc * Wc))));
        __half2 w24a = u2h(pack_h2(__ldg(kmp + (size_t)24 * (Hc * Wc)),
                                   __ldg(kmp + (size_t)49 * (Hc * Wc))));
        __half2 w24b = u2h(pack_h2(__ldg(kmp + (size_t)74 * (Hc * Wc)),
                                   __ldg(kmp + (size_t)99 * (Hc * Wc))));

        float* optr = out + ((size_t)((b << 8) + (g0 << 3) + (g << 2)) * 128
                             + 2 * h) * 128 + 2 * w;
        int rdBuf = 0;

        #pragma unroll 1
        for (int j = 0; j < cnt; j++) {
            // ---- commit prefetched unit j: convert fp32 -> half2 pairs, STS ----
            {
                __half2* dst = sgrp + rdBuf * GBUFH;
                uint4 s;
                s.x = pack_h2(pA[0].x, pA[1].x); s.y = pack_h2(pA[0].y, pA[1].y);
                s.z = pack_h2(pA[0].z, pA[1].z); s.w = pack_h2(pA[0].w, pA[1].w);
                *reinterpret_cast<uint4*>(dst + dA01) = s;
                s.x = pack_h2(pA[2].x, pA[3].x); s.y = pack_h2(pA[2].y, pA[3].y);
                s.z = pack_h2(pA[2].z, pA[3].z); s.w = pack_h2(pA[2].w, pA[3].w);
                *reinterpret_cast<uint4*>(dst + dA01 + PAIRH) = s;
                if (hasB) {
                    s.x = pack_h2(pB[0].x, pB[1].x); s.y = pack_h2(pB[0].y, pB[1].y);
                    s.z = pack_h2(pB[0].z, pB[1].z); s.w = pack_h2(pB[0].w, pB[1].w);
                    *reinterpret_cast<uint4*>(dst + dB01) = s;
                    s.x = pack_h2(pB[2].x, pB[3].x); s.y = pack_h2(pB[2].y, pB[3].y);
                    s.z = pack_h2(pB[2].z, pB[3].z); s.w = pack_h2(pB[2].w, pB[3].w);
                    *reinterpret_cast<uint4*>(dst + dB01 + PAIRH) = s;
                }
            }
            group_bar(g + 1);   // unit j visible; readers of j-3 long done

            // ---- prefetch unit j+1 (LDG latency hidden under compute) ----
            if (j + 1 < cnt) {
                base4 += U4;
                #pragma unroll
                for (int c = 0; c < 4; c++)
                    pA[c] = vA ? __ldg(x4 + base4 + c * CH4 + offA) : zf4;
                if (hasB) {
                    #pragma unroll
                    for (int c = 0; c < 4; c++)
                        pB[c] = vB ? __ldg(x4 + base4 + c * CH4 + offB) : zf4;
                }
            }

            // ---- compute 2 channel-pairs: 25 LDS + 100 HFMA2 each ----
            #pragma unroll
            for (int p = 0; p < 2; p++) {
                const __half2* sp = sgrp + rdBuf * GBUFH + p * PAIRH + (w + 2);
                const __half2 z = __half2half2(__float2half(0.f));
                __half2 A0=z,A1=z,A2=z,A3=z;   // taps 0..8
                __half2 B0=z,B1=z,B2=z,B3=z;   // taps 9..16
                __half2 C0=z,C1=z,C2=z,C3=z;   // taps 17..24

                #pragma unroll
                for (int p12 = 0; p12 < 12; p12++) {
                    const int k0 = 2 * p12, k1 = k0 + 1;
                    __half2 x0 = sp[(k0 / 5) * SROWH + (k0 % 5)];
                    __half2 x1 = sp[(k1 / 5) * SROWH + (k1 % 5)];
                    __half2 wv0 = wpk[p12],      wv1 = wpk[12 + p12];
                    __half2 wv2 = wpk[24 + p12], wv3 = wpk[36 + p12];
                    // tap k0: low halves of wpk
                    if (k0 < 9) {
                        A0 = __hfma2(blo(wv0), x0, A0); A1 = __hfma2(blo(wv1), x0, A1);
                        A2 = __hfma2(blo(wv2), x0, A2); A3 = __hfma2(blo(wv3), x0, A3);
                    } else if (k0 < 17) {
                        B0 = __hfma2(blo(wv0), x0, B0); B1 = __hfma2(blo(wv1), x0, B1);
                        B2 = __hfma2(blo(wv2), x0, B2); B3 = __hfma2(blo(wv3), x0, B3);
                    } else {
                        C0 = __hfma2(blo(wv0), x0, C0); C1 = __hfma2(blo(wv1), x0, C1);
                        C2 = __hfma2(blo(wv2), x0, C2); C3 = __hfma2(blo(wv3), x0, C3);
                    }
                    // tap k1: high halves
                    if (k1 < 9) {
                        A0 = __hfma2(bhi(wv0), x1, A0); A1 = __hfma2(bhi(wv1), x1, A1);
                        A2 = __hfma2(bhi(wv2), x1, A2); A3 = __hfma2(bhi(wv3), x1, A3);
                    } else if (k1 < 17) {
                        B0 = __hfma2(bhi(wv0), x1, B0); B1 = __hfma2(bhi(wv1), x1, B1);
                        B2 = __hfma2(bhi(wv2), x1, B2); B3 = __hfma2(bhi(wv3), x1, B3);
                    } else {
                        C0 = __hfma2(bhi(wv0), x1, C0); C1 = __hfma2(bhi(wv1), x1, C1);
                        C2 = __hfma2(bhi(wv2), x1, C2); C3 = __hfma2(bhi(wv3), x1, C3);
                    }
                }
                // tap 24
                {
                    __half2 x24 = sp[4 * SROWH + 4];
                    C0 = __hfma2(blo(w24a), x24, C0); C1 = __hfma2(bhi(w24a), x24, C1);
                    C2 = __hfma2(blo(w24b), x24, C2); C3 = __hfma2(bhi(w24b), x24, C3);
                }

                // epilogue: (A+B) fp16, cross-chain combine fp32
                float2 f0 = __half22float2(__hadd2(A0, B0)), c0 = __half22float2(C0);
                float2 f1 = __half22float2(__hadd2(A1, B1)), c1 = __half22float2(C1);
                float2 f2 = __half22float2(__hadd2(A2, B2)), c2 = __half22float2(C2);
                float2 f3 = __half22float2(__hadd2(A3, B3)), c3 = __half22float2(C3);

                // channel lo = 2p, hi = 2p+1 ; subpix u=i*2+j -> (2h+i, 2w+j)
                float* oA = optr + (size_t)(2 * p) * (128 * 128);
                float* oB = oA + (128 * 128);
                *reinterpret_cast<float2*>(oA)       = make_float2(f0.x + c0.x, f1.x + c1.x);
                *reinterpret_cast<float2*>(oA + 128) = make_float2(f2.x + c2.x, f3.x + c3.x);
                *reinterpret_cast<float2*>(oB)       = make_float2(f0.y + c0.y, f1.y + c1.y);
                *reinterpret_cast<float2*>(oB + 128) = make_float2(f2.y + c2.y, f3.y + c3.y);
            }
            optr += (size_t)8 * (128 * 128);

            rdBuf++; if (rdBuf == NBUF) rdBuf = 0;
        }

        u += cnt; rem -= cnt;
    }
}

extern "C" void kernel_launch(void* const* d_in, const int* in_sizes, int n_in,
                              void* d_out, int out_size)
{
    const float* x  = (const float*)d_in[0];   // [8,256,64,64]
    const float* km = (const float*)d_in[1];   // [8,100,64,64]
    float* out = (float*)d_out;                // [8,256,128,128]

    carafe_kernel<<<NCTA, THREADS>>>(x, km, out);
}